// round 12
// baseline (speedup 1.0000x reference)
#include <cuda_runtime.h>
#include <cuda_fp16.h>
#include <cstdint>

#define N_ROI 1024
#define FLAT  12544
#define HID   1024
#define EMB   256
#define MTOT  50176

// ---------------- scratch ----------------
__device__ __half g_f[(size_t)N_ROI * 196 * 256];    // NHWC fp16 features
__device__ __half g_cw[9 * 256 * 256];               // conv weights [tap][oc][ic]
__device__ __half g_w1[(size_t)HID * FLAT];          // [col][knew]
__device__ __half g_x[(size_t)N_ROI * FLAT];         // conv out fp16 [roi][o*256+oc]
__device__ float g_hp[4 * 1024 * 1024];              // fc1 split-K partials
__device__ float g_e[(size_t)N_ROI * EMB];
__device__ float g_eT[(size_t)EMB * N_ROI];

// ---------------- helpers ----------------
__device__ __forceinline__ uint32_t smem_u32(const void* p) {
    uint32_t a;
    asm("{ .reg .u64 t; cvta.to.shared.u64 t, %1; cvt.u32.u64 %0, t; }" : "=r"(a) : "l"(p));
    return a;
}
__device__ __forceinline__ void ldsm4(uint32_t& r0, uint32_t& r1, uint32_t& r2, uint32_t& r3,
                                      uint32_t addr) {
    asm volatile("ldmatrix.sync.aligned.m8n8.x4.shared.b16 {%0,%1,%2,%3}, [%4];"
                 : "=r"(r0), "=r"(r1), "=r"(r2), "=r"(r3) : "r"(addr));
}
__device__ __forceinline__ void mma16816(float* d, const uint32_t* a, uint32_t b0, uint32_t b1) {
    asm volatile(
        "mma.sync.aligned.m16n8k16.row.col.f32.f16.f16.f32 "
        "{%0,%1,%2,%3},{%4,%5,%6,%7},{%8,%9},{%0,%1,%2,%3};"
        : "+f"(d[0]), "+f"(d[1]), "+f"(d[2]), "+f"(d[3])
        : "r"(a[0]), "r"(a[1]), "r"(a[2]), "r"(a[3]), "r"(b0), "r"(b1));
}
__device__ __forceinline__ void cpa16(uint32_t dst, const void* src) {
    asm volatile("cp.async.ca.shared.global [%0], [%1], 16;" :: "r"(dst), "l"(src));
}
__device__ __forceinline__ void cpa16z(uint32_t dst, const void* src, uint32_t sz) {
    asm volatile("cp.async.ca.shared.global [%0], [%1], 16, %2;"
                 :: "r"(dst), "l"(src), "r"(sz));
}
__device__ __forceinline__ void cpa_commit() {
    asm volatile("cp.async.commit_group;" ::: "memory");
}
template <int N>
__device__ __forceinline__ void cpa_wait() {
    asm volatile("cp.async.wait_group %0;" :: "n"(N) : "memory");
}

// ---------------- fused prep: nhwc transpose | w1 transpose | conv-w convert --
__global__ __launch_bounds__(256) void prep_kernel(const float* __restrict__ feat,
                                                   const float* __restrict__ conv_w,
                                                   const float* __restrict__ w1) {
    __shared__ float sm[32 * 201];
    int b = blockIdx.x;
    if (b < 1024) {
        int n = b;
        const float* src = feat + (size_t)n * 50176;
        size_t obase = (size_t)n * 50176;
        float (*tile)[201] = (float(*)[201])sm;
        for (int cb = 0; cb < 8; cb++) {
            __syncthreads();
            for (int i = threadIdx.x; i < 6272; i += 256) {
                int c = i / 196, p = i % 196;
                tile[c][p] = src[(cb * 32 + c) * 196 + p];
            }
            __syncthreads();
            int c = threadIdx.x & 31, p0 = threadIdx.x >> 5;
            for (int p = p0; p < 196; p += 8)
                g_f[obase + (size_t)p * 256 + cb * 32 + c] = __float2half(tile[c][p]);
        }
    } else if (b < 1024 + 12544) {
        int idx = b - 1024;
        int knew0 = (idx % 392) * 32, col0 = (idx / 392) * 32;
        float (*t)[33] = (float(*)[33])sm;
        int tr = threadIdx.x >> 5, tc = threadIdx.x & 31;
#pragma unroll
        for (int i = 0; i < 4; i++) {
            int knew = knew0 + tr + i * 8;
            int oc = knew & 255, o = knew >> 8;
            t[tr + i * 8][tc] = w1[(size_t)(oc * 49 + o) * HID + col0 + tc];
        }
        __syncthreads();
#pragma unroll
        for (int i = 0; i < 4; i++) {
            int crow = tr + i * 8;
            g_w1[(size_t)(col0 + crow) * FLAT + knew0 + tc] = __float2half(t[tc][crow]);
        }
    } else {
        int i = (b - 13568) * 256 + threadIdx.x;
        int t = i >> 16, rem = i & 65535;
        int oc = rem >> 8, ic = rem & 255;
        g_cw[i] = __float2half(conv_w[oc * 2304 + ic * 9 + t]);
    }
}

// ---------------- single-pass fp16 HMMA GEMM, BK=64 chunks, 2-stage ----------
#define ROW_B 144
#define TILE_B (128 * ROW_B)
#define STAGE_B (2 * TILE_B)
template <int MODE>
__global__ __launch_bounds__(256, 2) void gemm_sp(const float* __restrict__ bias) {
    constexpr int TOTAL = MODE ? (3136 / 64) : (2304 / 64);
    extern __shared__ __align__(128) char smem[];
    uint32_t sb = smem_u32(smem);

    int tid = threadIdx.x, lane = tid & 31, wid = tid >> 5;
    int wm = wid >> 1, wn = wid & 1;
    int m0 = blockIdx.y * 128, n0 = blockIdx.x * 128;

    int rL = tid >> 2, sL = tid & 3;
    uint32_t dA0 = rL * ROW_B + sL * 16, dA1 = (rL + 64) * ROW_B + sL * 16;

    int ny0 = 0, oy0 = 0, ox0 = 0, ny1 = 0, oy1 = 0, ox1 = 0;
    size_t a0 = 0, a1 = 0, b0 = 0, b1 = 0;
    if (MODE == 0) {
        int rA0 = m0 + rL, rA1 = rA0 + 64;
        ny0 = rA0 / 49; int o0 = rA0 - ny0 * 49; oy0 = o0 / 7; ox0 = o0 - oy0 * 7;
        ny1 = rA1 / 49; int o1 = rA1 - ny1 * 49; oy1 = o1 / 7; ox1 = o1 - oy1 * 7;
    } else {
        size_t koff = (size_t)blockIdx.z * 3136;
        a0 = (size_t)(m0 + rL) * FLAT + koff + sL * 8;
        a1 = (size_t)(m0 + rL + 64) * FLAT + koff + sL * 8;
        b0 = (size_t)(n0 + rL) * FLAT + koff + sL * 8;
        b1 = (size_t)(n0 + rL + 64) * FLAT + koff + sL * 8;
    }

    float acc[2][8][4];
#pragma unroll
    for (int i = 0; i < 2; i++)
#pragma unroll
        for (int j = 0; j < 8; j++)
#pragma unroll
            for (int q = 0; q < 4; q++) acc[i][j][q] = 0.f;

    auto load_stage = [&](int it, int st) {
        uint32_t base = sb + st * STAGE_B;
        if (MODE == 0) {
            int t = it >> 2;
            int ky = t / 3, kx = t - ky * 3;
            int ic0 = ((it & 3) << 6) + sL * 8;
            int iy0 = 2 * oy0 + ky - 1, ix0 = 2 * ox0 + kx - 1;
            int iy1 = 2 * oy1 + ky - 1, ix1 = 2 * ox1 + kx - 1;
            uint32_t v0 = ((unsigned)iy0 < 14u && (unsigned)ix0 < 14u) ? 16u : 0u;
            uint32_t v1 = ((unsigned)iy1 < 14u && (unsigned)ix1 < 14u) ? 16u : 0u;
            size_t s0 = ((size_t)ny0 * 196 + (v0 ? iy0 * 14 + ix0 : 0)) * 256 + ic0;
            size_t s1 = ((size_t)ny1 * 196 + (v1 ? iy1 * 14 + ix1 : 0)) * 256 + ic0;
            size_t bw0 = (size_t)t * 65536 + (size_t)(n0 + rL) * 256 + ic0;
            cpa16z(base + dA0,              g_f + s0, v0);
            cpa16z(base + dA0 + 64,         g_f + s0 + 32, v0);
            cpa16z(base + dA1,              g_f + s1, v1);
            cpa16z(base + dA1 + 64,         g_f + s1 + 32, v1);
            cpa16(base + TILE_B + dA0,      g_cw + bw0);
            cpa16(base + TILE_B + dA0 + 64, g_cw + bw0 + 32);
            cpa16(base + TILE_B + dA1,      g_cw + bw0 + 64 * 256);
            cpa16(base + TILE_B + dA1 + 64, g_cw + bw0 + 64 * 256 + 32);
        } else {
            size_t ko = (size_t)it * 64;
            cpa16(base + dA0,               g_x + a0 + ko);
            cpa16(base + dA0 + 64,          g_x + a0 + ko + 32);
            cpa16(base + dA1,               g_x + a1 + ko);
            cpa16(base + dA1 + 64,          g_x + a1 + ko + 32);
            cpa16(base + TILE_B + dA0,      g_w1 + b0 + ko);
            cpa16(base + TILE_B + dA0 + 64, g_w1 + b0 + ko + 32);
            cpa16(base + TILE_B + dA1,      g_w1 + b1 + ko);
            cpa16(base + TILE_B + dA1 + 64, g_w1 + b1 + ko + 32);
        }
        cpa_commit();
    };

    uint32_t lmo = (lane & 15) * ROW_B + (lane >> 4) * 16;
    uint32_t aOff = wm * 32 * ROW_B + lmo;
    uint32_t bOff = wn * 64 * ROW_B + lmo;

    load_stage(0, 0);
    for (int it = 0; it < TOTAL; it++) {
        cpa_wait<0>();
        __syncthreads();
        if (it + 1 < TOTAL) load_stage(it + 1, (it + 1) & 1);

        uint32_t base = sb + (it & 1) * STAGE_B;
        uint32_t aA = base + aOff, bB = base + TILE_B + bOff;

#pragma unroll
        for (int ks = 0; ks < 4; ks++) {
            uint32_t a[2][4], b[8][2];
#pragma unroll
            for (int mt = 0; mt < 2; mt++)
                ldsm4(a[mt][0], a[mt][1], a[mt][2], a[mt][3],
                      aA + mt * 16 * ROW_B + ks * 32);
#pragma unroll
            for (int q = 0; q < 4; q++) {
                uint32_t r0, r1, r2, r3;
                ldsm4(r0, r1, r2, r3, bB + q * 16 * ROW_B + ks * 32);
                b[2 * q][0] = r0; b[2 * q][1] = r2;
                b[2 * q + 1][0] = r1; b[2 * q + 1][1] = r3;
            }
#pragma unroll
            for (int mt = 0; mt < 2; mt++)
#pragma unroll
                for (int nt = 0; nt < 8; nt++)
                    mma16816(acc[mt][nt], a[mt], b[nt][0], b[nt][1]);
        }
    }
    __syncthreads();

    int rbase = lane >> 2, cbase = (lane & 3) * 2;
#pragma unroll
    for (int mt = 0; mt < 2; mt++) {
#pragma unroll
        for (int nt = 0; nt < 8; nt++) {
            int n = n0 + wn * 64 + nt * 8 + cbase;
            float b0v = 0.f, b1v = 0.f;
            if (MODE == 0) { b0v = bias[n]; b1v = bias[n + 1]; }
#pragma unroll
            for (int half = 0; half < 2; half++) {
                int m = m0 + wm * 32 + mt * 16 + rbase + half * 8;
                if (MODE == 0) {
                    float v0 = fmaxf(acc[mt][nt][half * 2 + 0] + b0v, 0.f);
                    float v1 = fmaxf(acc[mt][nt][half * 2 + 1] + b1v, 0.f);
                    int roi = m / 49, o = m - roi * 49;
                    size_t dst = (size_t)roi * FLAT + o * 256 + n;
                    *(__half2*)&g_x[dst] = __floats2half2_rn(v0, v1);
                } else {
                    float2 v = make_float2(acc[mt][nt][half * 2 + 0],
                                           acc[mt][nt][half * 2 + 1]);
                    *(float2*)&g_hp[(size_t)blockIdx.z * 1048576 + (size_t)m * HID + n] = v;
                }
            }
        }
    }
}

// ---------------- fc2 (fused reduce+bias+relu) + L2-normalize, float4 k ------
__global__ __launch_bounds__(1024) void fc2_kernel(const float* __restrict__ w2,
                                                   const float* __restrict__ b1,
                                                   const float* __restrict__ b2) {
    extern __shared__ float dsm[];
    float* hs   = dsm;                       // [8][1024]
    float* part = dsm + 8192;                // [4][8][256]
    float* sred = dsm + 16384;               // [8][264]
    int n0 = blockIdx.x * 8;
    int tid = threadIdx.x, g = tid >> 8, c = tid & 255;

    for (int i = tid; i < 8192; i += 1024) {
        int r = i >> 10, k = i & 1023;
        size_t off = (size_t)(n0 + r) * HID + k;
        float s = g_hp[off] + g_hp[off + 1048576] + g_hp[off + 2097152] +
                  g_hp[off + 3145728] + b1[k];
        hs[r * 1024 + k] = fmaxf(s, 0.f);
    }
    __syncthreads();

    float acc[8];
#pragma unroll
    for (int r = 0; r < 8; r++) acc[r] = 0.f;
    int k0 = g * 256;
#pragma unroll 4
    for (int kk = 0; kk < 256; kk += 4) {
        const float* wp = w2 + (size_t)(k0 + kk) * 256 + c;
        float w0 = wp[0], w1v = wp[256], w2v = wp[512], w3v = wp[768];
#pragma unroll
        for (int r = 0; r < 8; r++) {
            float4 h4 = *(const float4*)&hs[r * 1024 + k0 + kk];
            acc[r] += h4.x * w0 + h4.y * w1v + h4.z * w2v + h4.w * w3v;
        }
    }
#pragma unroll
    for (int r = 0; r < 8; r++)
        part[(g * 8 + r) * 256 + c] = acc[r];
    __syncthreads();

    float val[2];
#pragma unroll
    for (int h = 0; h < 2; h++) {
        int r = g + h * 4;
        val[h] = part[(0 * 8 + r) * 256 + c] + part[(1 * 8 + r) * 256 + c] +
                 part[(2 * 8 + r) * 256 + c] + part[(3 * 8 + r) * 256 + c] + b2[c];
        sred[r * 264 + c] = val[h] * val[h];
    }
    __syncthreads();
    for (int s = 128; s > 0; s >>= 1) {
        if (c < s) {
            sred[g * 264 + c] += sred[g * 264 + c + s];
            sred[(g + 4) * 264 + c] += sred[(g + 4) * 264 + c + s];
        }
        __syncthreads();
    }
#pragma unroll
    for (int h = 0; h < 2; h++) {
        int r = g + h * 4;
        float v = val[h] / sqrtf(sred[r * 264]);
        g_e[(size_t)(n0 + r) * EMB + c] = v;
        g_eT[(size_t)c * N_ROI + (n0 + r)] = v;
    }
}

// ---------------- pairwise, float4 k ----------------
#define TI 16
__global__ __launch_bounds__(256) void pair_kernel(const float* __restrict__ wm,
                                                   const float* __restrict__ bm,
                                                   float* __restrict__ out) {
    int i0 = blockIdx.y * TI;
    int j0 = blockIdx.x * 256;
    if (j0 + 255 <= i0) return;

    __shared__ float ei[TI][256];
    __shared__ float wms[256];
    int tid = threadIdx.x;
    wms[tid] = wm[tid];
#pragma unroll
    for (int r = 0; r < TI; r++)
        ei[r][tid] = g_e[(size_t)(i0 + r) * EMB + tid];
    __syncthreads();

    int j = j0 + tid;
    float acc[TI];
#pragma unroll
    for (int r = 0; r < TI; r++) acc[r] = 0.f;

#pragma unroll 2
    for (int k = 0; k < 256; k += 4) {
        float4 w4 = *(const float4*)&wms[k];
        float vj0 = g_eT[(size_t)k * N_ROI + j];
        float vj1 = g_eT[(size_t)(k + 1) * N_ROI + j];
        float vj2 = g_eT[(size_t)(k + 2) * N_ROI + j];
        float vj3 = g_eT[(size_t)(k + 3) * N_ROI + j];
#pragma unroll
        for (int r = 0; r < TI; r++) {
            float4 e4 = *(const float4*)&ei[r][k];
            acc[r] += fabsf(e4.x - vj0) * w4.x + fabsf(e4.y - vj1) * w4.y +
                      fabsf(e4.z - vj2) * w4.z + fabsf(e4.w - vj3) * w4.w;
        }
    }

    float bmv = *bm;
#pragma unroll
    for (int r = 0; r < TI; r++) {
        int i = i0 + r;
        if (j > i) {
            int p = i * (2 * N_ROI - i - 1) / 2 + (j - i - 1);
            out[p] = acc[r] + bmv;
        }
    }
}

// ---------------- launch ----------------
extern "C" void kernel_launch(void* const* d_in, const int* in_sizes, int n_in,
                              void* d_out, int out_size) {
    const float* feat   = (const float*)d_in[0];
    const float* conv_w = (const float*)d_in[2];
    const float* conv_b = (const float*)d_in[3];
    const float* w1     = (const float*)d_in[4];
    const float* b1     = (const float*)d_in[5];
    const float* w2     = (const float*)d_in[6];
    const float* b2     = (const float*)d_in[7];
    const float* wm     = (const float*)d_in[8];
    const float* bm     = (const float*)d_in[9];
    float* out = (float*)d_out;

    const int SMEM = 2 * STAGE_B;
    const int F2SMEM = (8192 + 8192 + 8 * 264) * 4;
    static bool attr_set = false;
    if (!attr_set) {
        cudaFuncSetAttribute(gemm_sp<0>, cudaFuncAttributeMaxDynamicSharedMemorySize, SMEM);
        cudaFuncSetAttribute(gemm_sp<1>, cudaFuncAttributeMaxDynamicSharedMemorySize, SMEM);
        cudaFuncSetAttribute(fc2_kernel, cudaFuncAttributeMaxDynamicSharedMemorySize, F2SMEM);
        attr_set = true;
    }

    prep_kernel<<<1024 + 12544 + 2304, 256>>>(feat, conv_w, w1);
    gemm_sp<0><<<dim3(2, MTOT / 128), 256, SMEM>>>(conv_b);
    gemm_sp<1><<<dim3(HID / 128, N_ROI / 128, 4), 256, SMEM>>>(nullptr);
    fc2_kernel<<<N_ROI / 8, 1024, F2SMEM>>>(w2, b1, b2);
    pair_kernel<<<dim3(N_ROI / 256, N_ROI / TI), 256>>>(wm, bm, out);
}